// round 1
// baseline (speedup 1.0000x reference)
#include <cuda_runtime.h>
#include <cuda_bf16.h>
#include <cstdint>

// Problem constants (fixed shapes)
#define B_  4
#define S_  2048
#define D_  1024
#define H_  16
#define HD_ 64
#define M_  (B_ * S_)          // 8192 rows for all projection GEMMs
#define OUT_ELEMS ((size_t)B_ * S_ * D_)   // 8388608

// Scratch (allocation-free rule: __device__ globals)
__device__ float g_qh[OUT_ELEMS];    // Q projected, head-split [B,H,S,HD]
__device__ float g_attn[OUT_ELEMS];  // attention output, [B,S,D]

// ============================================================================
// GEMM: C[M,N] = A[M,K] @ W[N,K]^T + bias,  M=8192, N=K=1024
// Tile 128x64, BK=16, 256 threads, per-thread 8x4.
// mode 0: write C[m*N + n]  (plain [B,S,D])
// mode 1: write head-split [B,H,S,HD]: ((b*H+h)*S+s)*HD + hd
// ============================================================================
__global__ __launch_bounds__(256) void gemm_bias_kernel(
    const float* __restrict__ A, const float* __restrict__ W,
    const float* __restrict__ bias, float* __restrict__ C, int mode)
{
    const int Kd = D_;   // 1024
    const int Nd = D_;   // 1024
    __shared__ float As[16][132];  // As[kk][m], pitch 132 (float4-aligned)
    __shared__ float Bs[16][68];   // Bs[kk][n]

    const int tid = threadIdx.x;
    const int tx = tid & 15;       // 0..15 -> 4 cols each
    const int ty = tid >> 4;       // 0..15 -> 8 rows each
    const int m0 = blockIdx.y * 128;
    const int n0 = blockIdx.x * 64;

    // loaders
    const int lrA = tid >> 1;            // 0..127
    const int lkA = (tid & 1) * 8;       // 0 or 8
    const int lrB = tid >> 2;            // 0..63
    const int lkB = (tid & 3) * 4;       // 0,4,8,12

    const float* aptr = A + (size_t)(m0 + lrA) * Kd + lkA;
    const float* wptr = W + (size_t)(n0 + lrB) * Kd + lkB;

    float acc[8][4];
    #pragma unroll
    for (int r = 0; r < 8; r++)
        #pragma unroll
        for (int c = 0; c < 4; c++) acc[r][c] = 0.f;

    for (int k0 = 0; k0 < Kd; k0 += 16) {
        __syncthreads();
        // load A tile: 2 float4 per thread -> As[kk][m]
        float4 a0 = *(const float4*)(aptr + k0);
        float4 a1 = *(const float4*)(aptr + k0 + 4);
        As[lkA + 0][lrA] = a0.x; As[lkA + 1][lrA] = a0.y;
        As[lkA + 2][lrA] = a0.z; As[lkA + 3][lrA] = a0.w;
        As[lkA + 4][lrA] = a1.x; As[lkA + 5][lrA] = a1.y;
        As[lkA + 6][lrA] = a1.z; As[lkA + 7][lrA] = a1.w;
        // load W tile: 1 float4 per thread -> Bs[kk][n]
        float4 w0 = *(const float4*)(wptr + k0);
        Bs[lkB + 0][lrB] = w0.x; Bs[lkB + 1][lrB] = w0.y;
        Bs[lkB + 2][lrB] = w0.z; Bs[lkB + 3][lrB] = w0.w;
        __syncthreads();

        #pragma unroll
        for (int kk = 0; kk < 16; kk++) {
            float4 a4a = *(const float4*)(&As[kk][ty * 8]);
            float4 a4b = *(const float4*)(&As[kk][ty * 8 + 4]);
            float4 b4  = *(const float4*)(&Bs[kk][tx * 4]);
            float aa[8] = {a4a.x, a4a.y, a4a.z, a4a.w, a4b.x, a4b.y, a4b.z, a4b.w};
            float bb[4] = {b4.x, b4.y, b4.z, b4.w};
            #pragma unroll
            for (int r = 0; r < 8; r++)
                #pragma unroll
                for (int c = 0; c < 4; c++)
                    acc[r][c] = fmaf(aa[r], bb[c], acc[r][c]);
        }
    }

    // epilogue
    const int nbase = n0 + tx * 4;
    float4 bv = *(const float4*)(bias + nbase);
    const float bb[4] = {bv.x, bv.y, bv.z, bv.w};

    #pragma unroll
    for (int r = 0; r < 8; r++) {
        int m = m0 + ty * 8 + r;
        float4 o = make_float4(acc[r][0] + bb[0], acc[r][1] + bb[1],
                               acc[r][2] + bb[2], acc[r][3] + bb[3]);
        if (mode == 0) {
            *(float4*)(C + (size_t)m * Nd + nbase) = o;
        } else {
            int b = m >> 11;          // m / 2048
            int s = m & 2047;
            int h = nbase >> 6;
            int hd = nbase & 63;
            *(float4*)(C + (((size_t)(b * H_ + h) * S_ + s) << 6) + hd) = o;
        }
    }
}

// ============================================================================
// Flash attention, causal, fp32. One block = 64 query rows of one (b,h).
// 256 threads (16x16), per-thread 4x4. Tiles 64x64, HD=64.
// Q,K staged transposed (Qs[d][r]); P staged transposed (Pt[j][r]); V natural.
// ============================================================================
#define FPITCH 68
#define FLASH_SMEM (4 * 64 * FPITCH * 4)   // 69632 bytes

__global__ __launch_bounds__(256) void flash_kernel(
    const float* __restrict__ Qh, const float* __restrict__ Kh,
    const float* __restrict__ Vh, float* __restrict__ Out)
{
    extern __shared__ float sm[];
    float* Qs = sm;                      // [64][68]  Qs[d][r]
    float* Ks = Qs + 64 * FPITCH;        // Ks[d][j]
    float* Vs = Ks + 64 * FPITCH;        // Vs[j][c]
    float* Pt = Vs + 64 * FPITCH;        // Pt[j][r]

    const int tid = threadIdx.x;
    const int tx = tid & 15;
    const int ty = tid >> 4;
    const int bh = blockIdx.y;           // b*H + h
    const int qblk = blockIdx.x;
    const int q0 = qblk * 64;

    const float* Qbase = Qh + ((size_t)bh * S_ + q0) * HD_;
    const float* Kbase = Kh + (size_t)bh * S_ * HD_;
    const float* Vbase = Vh + (size_t)bh * S_ * HD_;

    // load Q tile transposed
    {
        int r = tid >> 2;                // 0..63
        int dchunk = (tid & 3) * 16;
        const float4* src = (const float4*)(Qbase + (size_t)r * HD_ + dchunk);
        #pragma unroll
        for (int i = 0; i < 4; i++) {
            float4 v = src[i];
            int d = dchunk + i * 4;
            Qs[(d + 0) * FPITCH + r] = v.x;
            Qs[(d + 1) * FPITCH + r] = v.y;
            Qs[(d + 2) * FPITCH + r] = v.z;
            Qs[(d + 3) * FPITCH + r] = v.w;
        }
    }

    float m_i[4], l_i[4], acc[4][4];
    #pragma unroll
    for (int r = 0; r < 4; r++) {
        m_i[r] = -1e30f; l_i[r] = 0.f;
        #pragma unroll
        for (int c = 0; c < 4; c++) acc[r][c] = 0.f;
    }

    const int nkb = qblk + 1;            // causal: key blocks 0..qblk
    for (int kb = 0; kb < nkb; kb++) {
        const int k0 = kb * 64;
        __syncthreads();  // protect Ks/Vs/Pt reuse (also covers Qs on kb==0)
        {
            int j = tid >> 2;
            int dchunk = (tid & 3) * 16;
            const float4* ksrc = (const float4*)(Kbase + (size_t)(k0 + j) * HD_ + dchunk);
            #pragma unroll
            for (int i = 0; i < 4; i++) {
                float4 v = ksrc[i];
                int d = dchunk + i * 4;
                Ks[(d + 0) * FPITCH + j] = v.x;
                Ks[(d + 1) * FPITCH + j] = v.y;
                Ks[(d + 2) * FPITCH + j] = v.z;
                Ks[(d + 3) * FPITCH + j] = v.w;
            }
            const float4* vsrc = (const float4*)(Vbase + (size_t)(k0 + j) * HD_ + dchunk);
            float4* vdst = (float4*)(Vs + j * FPITCH + dchunk);
            #pragma unroll
            for (int i = 0; i < 4; i++) vdst[i] = vsrc[i];
        }
        __syncthreads();

        // scores: rows ty*4+r, keys tx*4+c
        float s[4][4];
        #pragma unroll
        for (int r = 0; r < 4; r++)
            #pragma unroll
            for (int c = 0; c < 4; c++) s[r][c] = 0.f;
        #pragma unroll
        for (int d = 0; d < 64; d++) {
            float4 qv = *(const float4*)(Qs + d * FPITCH + ty * 4);
            float4 kv = *(const float4*)(Ks + d * FPITCH + tx * 4);
            float qa[4] = {qv.x, qv.y, qv.z, qv.w};
            float ka[4] = {kv.x, kv.y, kv.z, kv.w};
            #pragma unroll
            for (int r = 0; r < 4; r++)
                #pragma unroll
                for (int c = 0; c < 4; c++)
                    s[r][c] = fmaf(qa[r], ka[c], s[r][c]);
        }

        const bool diag = (kb == qblk);
        #pragma unroll
        for (int r = 0; r < 4; r++) {
            int gi = q0 + ty * 4 + r;
            #pragma unroll
            for (int c = 0; c < 4; c++) {
                int gj = k0 + tx * 4 + c;
                float v = s[r][c] * 0.125f;   // 1/sqrt(64)
                // reference adds -1e5; exp underflows to exactly 0 either way
                if (diag && gj > gi) v = -1e30f;
                s[r][c] = v;
            }
        }

        // online softmax
        float mscale[4];
        #pragma unroll
        for (int r = 0; r < 4; r++) {
            float m = fmaxf(fmaxf(s[r][0], s[r][1]), fmaxf(s[r][2], s[r][3]));
            #pragma unroll
            for (int off = 1; off < 16; off <<= 1)
                m = fmaxf(m, __shfl_xor_sync(0xffffffffu, m, off));
            float mnew = fmaxf(m_i[r], m);
            mscale[r] = __expf(m_i[r] - mnew);
            m_i[r] = mnew;
            float sum = 0.f;
            #pragma unroll
            for (int c = 0; c < 4; c++) {
                float p = __expf(s[r][c] - mnew);
                s[r][c] = p;
                sum += p;
            }
            #pragma unroll
            for (int off = 1; off < 16; off <<= 1)
                sum += __shfl_xor_sync(0xffffffffu, sum, off);
            l_i[r] = l_i[r] * mscale[r] + sum;
        }

        // stage P transposed: Pt[j][r]
        #pragma unroll
        for (int c = 0; c < 4; c++) {
            float4 pv = make_float4(s[0][c], s[1][c], s[2][c], s[3][c]);
            *(float4*)(Pt + (tx * 4 + c) * FPITCH + ty * 4) = pv;
        }
        __syncthreads();

        // acc = acc*mscale + P @ V
        #pragma unroll
        for (int r = 0; r < 4; r++)
            #pragma unroll
            for (int c = 0; c < 4; c++) acc[r][c] *= mscale[r];
        #pragma unroll
        for (int j = 0; j < 64; j++) {
            float4 pv = *(const float4*)(Pt + j * FPITCH + ty * 4);
            float4 vv = *(const float4*)(Vs + j * FPITCH + tx * 4);
            float pa[4] = {pv.x, pv.y, pv.z, pv.w};
            float va[4] = {vv.x, vv.y, vv.z, vv.w};
            #pragma unroll
            for (int r = 0; r < 4; r++)
                #pragma unroll
                for (int c = 0; c < 4; c++)
                    acc[r][c] = fmaf(pa[r], va[c], acc[r][c]);
        }
    }

    // epilogue: write [B,S,D]
    const int b = bh >> 4;   // / H_
    const int h = bh & 15;
    #pragma unroll
    for (int r = 0; r < 4; r++) {
        float inv = 1.f / l_i[r];
        int gs = q0 + ty * 4 + r;
        float4 o = make_float4(acc[r][0] * inv, acc[r][1] * inv,
                               acc[r][2] * inv, acc[r][3] * inv);
        *(float4*)(Out + ((size_t)(b * S_ + gs)) * D_ + h * 64 + tx * 4) = o;
    }
}

// ============================================================================
// Launch
// ============================================================================
extern "C" void kernel_launch(void* const* d_in, const int* in_sizes, int n_in,
                              void* d_out, int out_size)
{
    const float* q  = (const float*)d_in[0];
    const float* k  = (const float*)d_in[1];
    const float* v  = (const float*)d_in[2];
    // d_in[3] = mask (causal triu; handled analytically)
    const float* Wq = (const float*)d_in[4];
    const float* bq = (const float*)d_in[5];
    const float* Wk = (const float*)d_in[6];
    const float* bk = (const float*)d_in[7];
    const float* Wv = (const float*)d_in[8];
    const float* bv = (const float*)d_in[9];
    const float* Wo = (const float*)d_in[10];
    const float* bo = (const float*)d_in[11];

    float* out = (float*)d_out;                 // [B,S,D]
    float* kh  = out + OUT_ELEMS;               // [B,H,S,HD]
    float* vh  = out + 2 * OUT_ELEMS;           // [B,H,S,HD]

    float* qh;   cudaGetSymbolAddress((void**)&qh,   g_qh);
    float* attn; cudaGetSymbolAddress((void**)&attn, g_attn);

    dim3 ggrid(D_ / 64, M_ / 128);              // (16, 64)
    dim3 gblk(256);

    gemm_bias_kernel<<<ggrid, gblk>>>(q, Wq, bq, qh, 1);
    gemm_bias_kernel<<<ggrid, gblk>>>(k, Wk, bk, kh, 1);
    gemm_bias_kernel<<<ggrid, gblk>>>(v, Wv, bv, vh, 1);

    cudaFuncSetAttribute(flash_kernel,
                         cudaFuncAttributeMaxDynamicSharedMemorySize, FLASH_SMEM);
    flash_kernel<<<dim3(S_ / 64, B_ * H_), 256, FLASH_SMEM>>>(qh, kh, vh, attn);

    gemm_bias_kernel<<<ggrid, gblk>>>(attn, Wo, bo, out, 0);
}

// round 5
// speedup vs baseline: 1.5163x; 1.5163x over previous
#include <cuda_runtime.h>
#include <cuda_fp16.h>
#include <cstdint>

// Problem constants
#define B_  4
#define S_  2048
#define D_  1024
#define H_  16
#define HD_ 64
#define M_  (B_ * S_)
#define OUT_ELEMS ((size_t)B_ * S_ * D_)

// Scratch
__device__ float g_qh[OUT_ELEMS];
__device__ float g_attn[OUT_ELEMS];

__device__ __forceinline__ uint32_t smem_u32(const void* p) {
    uint32_t a;
    asm("{ .reg .u64 t; cvta.to.shared.u64 t, %1; cvt.u32.u64 %0, t; }" : "=r"(a) : "l"(p));
    return a;
}
__device__ __forceinline__ uint32_t sw128(uint32_t off) { return off ^ ((off >> 3) & 0x70); }

__device__ __forceinline__ void ldsm_x4(uint32_t* r, uint32_t addr) {
    asm volatile("ldmatrix.sync.aligned.m8n8.x4.shared.b16 {%0,%1,%2,%3}, [%4];"
        : "=r"(r[0]), "=r"(r[1]), "=r"(r[2]), "=r"(r[3]) : "r"(addr));
}
__device__ __forceinline__ void mma_f16(float* d, const uint32_t* a, const uint32_t* b) {
    asm volatile(
        "mma.sync.aligned.m16n8k16.row.col.f32.f16.f16.f32 "
        "{%0,%1,%2,%3}, {%4,%5,%6,%7}, {%8,%9}, {%0,%1,%2,%3};"
        : "+f"(d[0]), "+f"(d[1]), "+f"(d[2]), "+f"(d[3])
        : "r"(a[0]), "r"(a[1]), "r"(a[2]), "r"(a[3]), "r"(b[0]), "r"(b[1]));
}

// ============================================================================
// HMMA GEMM: C[M,N] = A[M,K] @ W[N,K]^T + bias, fp16 hi/lo split (3 mma terms).
// Tile 128x128, BK=64, 256 threads (8 warps 2x4), SW128 fp16 smem.
// smem: AHI@0, ALO@16K, BHI@32K, BLO@48K  (each 128 rows x 128B)
// ============================================================================
#define GEMM_SMEM 65536

__device__ __forceinline__ void split_store(char* smem_hi_base, uint32_t off, float4 v) {
    __half hx = __float2half_rn(v.x), hy = __float2half_rn(v.y);
    __half hz = __float2half_rn(v.z), hw = __float2half_rn(v.w);
    __half lx = __float2half_rn(v.x - __half2float(hx));
    __half ly = __float2half_rn(v.y - __half2float(hy));
    __half lz = __float2half_rn(v.z - __half2float(hz));
    __half lw = __float2half_rn(v.w - __half2float(hw));
    uint32_t hi01 = (uint32_t)__half_as_ushort(hx) | ((uint32_t)__half_as_ushort(hy) << 16);
    uint32_t hi23 = (uint32_t)__half_as_ushort(hz) | ((uint32_t)__half_as_ushort(hw) << 16);
    uint32_t lo01 = (uint32_t)__half_as_ushort(lx) | ((uint32_t)__half_as_ushort(ly) << 16);
    uint32_t lo23 = (uint32_t)__half_as_ushort(lz) | ((uint32_t)__half_as_ushort(lw) << 16);
    *(uint2*)(smem_hi_base + off)         = make_uint2(hi01, hi23);
    *(uint2*)(smem_hi_base + 16384 + off) = make_uint2(lo01, lo23);
}

__global__ __launch_bounds__(256, 2) void gemm_hmma_kernel(
    const float* __restrict__ A0, const float* __restrict__ A1, const float* __restrict__ A2,
    const float* __restrict__ W0, const float* __restrict__ W1, const float* __restrict__ W2,
    const float* __restrict__ bi0, const float* __restrict__ bi1, const float* __restrict__ bi2,
    float* __restrict__ C0, float* __restrict__ C1, float* __restrict__ C2, int mode)
{
    extern __shared__ char sm[];
    const uint32_t smb = smem_u32(sm);
    const int tid = threadIdx.x;
    const int lane = tid & 31;
    const int wid = tid >> 5;
    const int wm = wid >> 2;           // 0..1 -> 64 rows
    const int wn = wid & 3;            // 0..3 -> 32 cols
    const int z = blockIdx.z;
    const float* A = (z == 0) ? A0 : (z == 1) ? A1 : A2;
    const float* W = (z == 0) ? W0 : (z == 1) ? W1 : W2;
    const float* bias = (z == 0) ? bi0 : (z == 1) ? bi1 : bi2;
    float* C = (z == 0) ? C0 : (z == 1) ? C1 : C2;

    const int m0 = blockIdx.y * 128;
    const int n0 = blockIdx.x * 128;

    float acc[4][4][4];
    #pragma unroll
    for (int i = 0; i < 4; i++)
        #pragma unroll
        for (int j = 0; j < 4; j++)
            #pragma unroll
            for (int t = 0; t < 4; t++) acc[i][j][t] = 0.f;

    // ldmatrix lane address components
    const int a_m = lane & 15;                               // m row within 16
    const int a_kb = (lane >> 4) * 16;                       // 0 or 16 bytes (k half)
    const int b_n = (lane & 7) + ((lane >> 4) & 1) * 8;      // n row within 16
    const int b_kb = ((lane >> 3) & 1) * 16;                 // k half bytes

    const int lrow = tid >> 4;                               // loader row group base
    const int lc4 = (tid & 15) * 4;

    for (int ch = 0; ch < 16; ch++) {
        const int k0 = ch * 64;
        __syncthreads();
        // Load 128x64 fp32 of A and W, split to fp16 hi/lo, swizzled store.
        #pragma unroll
        for (int i = 0; i < 8; i++) {
            int row = lrow + i * 16;
            float4 av = *(const float4*)(A + (size_t)(m0 + row) * D_ + k0 + lc4);
            float4 wv = *(const float4*)(W + (size_t)(n0 + row) * D_ + k0 + lc4);
            uint32_t off = sw128((uint32_t)(row * 128 + lc4 * 2));
            split_store(sm, off, av);            // A -> 0 / 16K
            split_store(sm + 32768, off, wv);    // W -> 32K / 48K
        }
        __syncthreads();

        #pragma unroll
        for (int ks = 0; ks < 4; ks++) {
            // A fragments (hi & lo), 4 m-tiles
            uint32_t afh[4][4], afl[4][4];
            #pragma unroll
            for (int mt = 0; mt < 4; mt++) {
                uint32_t byte = (uint32_t)((wm * 64 + mt * 16 + a_m) * 128 + ks * 32 + a_kb);
                uint32_t ad = smb + sw128(byte);
                ldsm_x4(afh[mt], ad);
                ldsm_x4(afl[mt], ad + 16384);
            }
            // B fragments (hi & lo), 2 x4 loads cover 4 n8-tiles
            uint32_t bfh[2][4], bfl[2][4];
            #pragma unroll
            for (int bt = 0; bt < 2; bt++) {
                uint32_t byte = (uint32_t)((wn * 32 + bt * 16 + b_n) * 128 + ks * 32 + b_kb);
                uint32_t bd = smb + 32768 + sw128(byte);
                ldsm_x4(bfh[bt], bd);
                ldsm_x4(bfl[bt], bd + 16384);
            }
            #pragma unroll
            for (int mt = 0; mt < 4; mt++)
                #pragma unroll
                for (int nt = 0; nt < 4; nt++) {
                    const uint32_t* bh = &bfh[nt >> 1][(nt & 1) * 2];
                    const uint32_t* bl = &bfl[nt >> 1][(nt & 1) * 2];
                    mma_f16(acc[mt][nt], afh[mt], bh);   // hi*hi
                    mma_f16(acc[mt][nt], afh[mt], bl);   // hi*lo
                    mma_f16(acc[mt][nt], afl[mt], bh);   // lo*hi
                }
        }
    }

    // Epilogue: register accumulators -> gmem (float2 per fragment row)
    const int g = lane >> 2;
    const int q2 = (lane & 3) * 2;
    #pragma unroll
    for (int mt = 0; mt < 4; mt++) {
        #pragma unroll
        for (int nt = 0; nt < 4; nt++) {
            int mr = m0 + wm * 64 + mt * 16 + g;
            int nc = n0 + wn * 32 + nt * 8 + q2;
            float2 b2 = *(const float2*)(bias + nc);
            #pragma unroll
            for (int half = 0; half < 2; half++) {
                int m = mr + half * 8;
                float2 o = make_float2(acc[mt][nt][half * 2 + 0] + b2.x,
                                       acc[mt][nt][half * 2 + 1] + b2.y);
                float* dst;
                if (mode == 0) {
                    dst = C + (size_t)m * D_ + nc;
                } else {
                    int b = m >> 11, s = m & 2047, h = nc >> 6, hd = nc & 63;
                    dst = C + (((size_t)(b * H_ + h) * S_ + s) << 6) + hd;
                }
                *(float2*)dst = o;
            }
        }
    }
}

// ============================================================================
// Flash attention fp32, tiles 128(q) x 64(k), 256 threads, 8x4 per thread.
// Qs/Pt transposed (r-indexed, broadcast reads), Ks transposed, Vs natural.
// ============================================================================
#define FP2 132
#define FP1 68
#define FLASH_SMEM (64 * (FP2 + FP1 + FP1 + FP2) * 4)   // 102400

__global__ __launch_bounds__(256, 2) void flash_kernel(
    const float* __restrict__ Qh, const float* __restrict__ Kh,
    const float* __restrict__ Vh, float* __restrict__ Out)
{
    extern __shared__ float smf[];
    float* Qs = smf;                     // [64][FP2]  Qs[d][r], r<128
    float* Ks = Qs + 64 * FP2;           // [64][FP1]  Ks[d][j]
    float* Vs = Ks + 64 * FP1;           // [64][FP1]  Vs[j][c]
    float* Pt = Vs + 64 * FP1;           // [64][FP2]  Pt[j][r]

    const int tid = threadIdx.x;
    const int tx = tid & 15;             // 4 key-cols
    const int ty = tid >> 4;             // 8 q-rows
    const int bh = blockIdx.y;
    const int qblk = (int)gridDim.x - 1 - (int)blockIdx.x;  // heavy blocks first
    const int q0 = qblk * 128;

    const float* Qbase = Qh + ((size_t)bh * S_ + q0) * HD_;
    const float* Kbase = Kh + (size_t)bh * S_ * HD_;
    const float* Vbase = Vh + (size_t)bh * S_ * HD_;

    // load Q tile transposed: 128 rows x 64 d = 2048 float4
    #pragma unroll
    for (int i = 0; i < 8; i++) {
        int idx = tid + i * 256;
        int r = idx >> 4;
        int c4 = (idx & 15) * 4;
        float4 v = *(const float4*)(Qbase + (size_t)r * HD_ + c4);
        Qs[(c4 + 0) * FP2 + r] = v.x;
        Qs[(c4 + 1) * FP2 + r] = v.y;
        Qs[(c4 + 2) * FP2 + r] = v.z;
        Qs[(c4 + 3) * FP2 + r] = v.w;
    }

    float m_i[8], l_i[8], acc[8][4];
    #pragma unroll
    for (int r = 0; r < 8; r++) {
        m_i[r] = -1e30f; l_i[r] = 0.f;
        #pragma unroll
        for (int c = 0; c < 4; c++) acc[r][c] = 0.f;
    }

    const int nkb = 2 * qblk + 2;
    for (int kb = 0; kb < nkb; kb++) {
        const int k0 = kb * 64;
        __syncthreads();
        // load K (transposed) and V (natural): 64x64 = 1024 float4
        #pragma unroll
        for (int i = 0; i < 4; i++) {
            int idx = tid + i * 256;
            int j = idx >> 4;
            int c4 = (idx & 15) * 4;
            float4 kv = *(const float4*)(Kbase + (size_t)(k0 + j) * HD_ + c4);
            Ks[(c4 + 0) * FP1 + j] = kv.x;
            Ks[(c4 + 1) * FP1 + j] = kv.y;
            Ks[(c4 + 2) * FP1 + j] = kv.z;
            Ks[(c4 + 3) * FP1 + j] = kv.w;
            float4 vv = *(const float4*)(Vbase + (size_t)(k0 + j) * HD_ + c4);
            *(float4*)(Vs + j * FP1 + c4) = vv;
        }
        __syncthreads();

        // scores: rows ty*8+r, keys tx*4+c
        float s[8][4];
        #pragma unroll
        for (int r = 0; r < 8; r++)
            #pragma unroll
            for (int c = 0; c < 4; c++) s[r][c] = 0.f;
        #pragma unroll
        for (int d = 0; d < 64; d++) {
            float4 qa4 = *(const float4*)(Qs + d * FP2 + ty * 8);
            float4 qb4 = *(const float4*)(Qs + d * FP2 + ty * 8 + 4);
            float4 kv4 = *(const float4*)(Ks + d * FP1 + tx * 4);
            float qa[8] = {qa4.x, qa4.y, qa4.z, qa4.w, qb4.x, qb4.y, qb4.z, qb4.w};
            float ka[4] = {kv4.x, kv4.y, kv4.z, kv4.w};
            #pragma unroll
            for (int r = 0; r < 8; r++)
                #pragma unroll
                for (int c = 0; c < 4; c++)
                    s[r][c] = fmaf(qa[r], ka[c], s[r][c]);
        }

        const bool diag = (kb >= 2 * qblk);
        #pragma unroll
        for (int r = 0; r < 8; r++) {
            int gi = q0 + ty * 8 + r;
            #pragma unroll
            for (int c = 0; c < 4; c++) {
                float v = s[r][c] * 0.125f;     // 1/sqrt(64)
                if (diag && (k0 + tx * 4 + c) > gi) v = -1e30f;
                s[r][c] = v;
            }
        }

        // online softmax (row groups of 16 threads; shfl widths stay in-group)
        float mscale[8];
        #pragma unroll
        for (int r = 0; r < 8; r++) {
            float m = fmaxf(fmaxf(s[r][0], s[r][1]), fmaxf(s[r][2], s[r][3]));
            #pragma unroll
            for (int off = 1; off < 16; off <<= 1)
                m = fmaxf(m, __shfl_xor_sync(0xffffffffu, m, off));
            float mnew = fmaxf(m_i[r], m);
            mscale[r] = __expf(m_i[r] - mnew);
            m_i[r] = mnew;
            float sum = 0.f;
            #pragma unroll
            for (int c = 0; c < 4; c++) {
                float p = __expf(s[r][c] - mnew);
                s[r][c] = p;
                sum += p;
            }
            #pragma unroll
            for (int off = 1; off < 16; off <<= 1)
                sum += __shfl_xor_sync(0xffffffffu, sum, off);
            l_i[r] = l_i[r] * mscale[r] + sum;
        }

        // stage P transposed: Pt[j][r]
        #pragma unroll
        for (int c = 0; c < 4; c++) {
            int j = tx * 4 + c;
            *(float4*)(Pt + j * FP2 + ty * 8) =
                make_float4(s[0][c], s[1][c], s[2][c], s[3][c]);
            *(float4*)(Pt + j * FP2 + ty * 8 + 4) =
                make_float4(s[4][c], s[5][c], s[6][c], s[7][c]);
        }
        __syncthreads();

        #pragma unroll
        for (int r = 0; r < 8; r++)
            #pragma unroll
            for (int c = 0; c < 4; c++) acc[r][c] *= mscale[r];
        #pragma unroll
        for (int j = 0; j < 64; j++) {
            float4 pa4 = *(const float4*)(Pt + j * FP2 + ty * 8);
            float4 pb4 = *(const float4*)(Pt + j * FP2 + ty * 8 + 4);
            float4 vv4 = *(const float4*)(Vs + j * FP1 + tx * 4);
            float pa[8] = {pa4.x, pa4.y, pa4.z, pa4.w, pb4.x, pb4.y, pb4.z, pb4.w};
            float va[4] = {vv4.x, vv4.y, vv4.z, vv4.w};
            #pragma unroll
            for (int r = 0; r < 8; r++)
                #pragma unroll
                for (int c = 0; c < 4; c++)
                    acc[r][c] = fmaf(pa[r], va[c], acc[r][c]);
        }
    }

    const int b = bh >> 4;
    const int h = bh & 15;
    #pragma unroll
    for (int r = 0; r < 8; r++) {
        float inv = 1.f / l_i[r];
        int gs = q0 + ty * 8 + r;
        float4 o = make_float4(acc[r][0] * inv, acc[r][1] * inv,
                               acc[r][2] * inv, acc[r][3] * inv);
        *(float4*)(Out + ((size_t)(b * S_ + gs)) * D_ + h * 64 + tx * 4) = o;
    }
}

// ============================================================================
// Launch
// ============================================================================
extern "C" void kernel_launch(void* const* d_in, const int* in_sizes, int n_in,
                              void* d_out, int out_size)
{
    const float* q  = (const float*)d_in[0];
    const float* k  = (const float*)d_in[1];
    const float* v  = (const float*)d_in[2];
    const float* Wq = (const float*)d_in[4];
    const float* bq = (const float*)d_in[5];
    const float* Wk = (const float*)d_in[6];
    const float* bk = (const float*)d_in[7];
    const float* Wv = (const float*)d_in[8];
    const float* bv = (const float*)d_in[9];
    const float* Wo = (const float*)d_in[10];
    const float* bo = (const float*)d_in[11];

    float* out = (float*)d_out;
    float* kh  = out + OUT_ELEMS;
    float* vh  = out + 2 * OUT_ELEMS;

    float* qh;   cudaGetSymbolAddress((void**)&qh,   g_qh);
    float* attn; cudaGetSymbolAddress((void**)&attn, g_attn);

    cudaFuncSetAttribute(gemm_hmma_kernel,
                         cudaFuncAttributeMaxDynamicSharedMemorySize, GEMM_SMEM);
    cudaFuncSetAttribute(flash_kernel,
                         cudaFuncAttributeMaxDynamicSharedMemorySize, FLASH_SMEM);

    dim3 qkv_grid(D_ / 128, M_ / 128, 3);       // (8, 64, 3)
    gemm_hmma_kernel<<<qkv_grid, 256, GEMM_SMEM>>>(
        q, k, v, Wq, Wk, Wv, bq, bk, bv, qh, kh, vh, 1);

    flash_kernel<<<dim3(S_ / 128, B_ * H_), 256, FLASH_SMEM>>>(qh, kh, vh, attn);

    dim3 o_grid(D_ / 128, M_ / 128, 1);
    gemm_hmma_kernel<<<o_grid, 256, GEMM_SMEM>>>(
        attn, attn, attn, Wo, Wo, Wo, bo, bo, bo, out, out, out, 0);
}

// round 7
// speedup vs baseline: 2.3205x; 1.5304x over previous
#include <cuda_runtime.h>
#include <cuda_fp16.h>
#include <cstdint>

// Problem constants
#define B_  4
#define S_  2048
#define D_  1024
#define H_  16
#define HD_ 64
#define M_  (B_ * S_)
#define OUT_ELEMS ((size_t)B_ * S_ * D_)

// Scratch
__device__ float g_qh[OUT_ELEMS];
__device__ float g_attn[OUT_ELEMS];

__device__ __forceinline__ uint32_t smem_u32(const void* p) {
    uint32_t a;
    asm("{ .reg .u64 t; cvta.to.shared.u64 t, %1; cvt.u32.u64 %0, t; }" : "=r"(a) : "l"(p));
    return a;
}
__device__ __forceinline__ uint32_t sw128(uint32_t off) { return off ^ ((off >> 3) & 0x70); }

__device__ __forceinline__ void ldsm_x4(uint32_t* r, uint32_t addr) {
    asm volatile("ldmatrix.sync.aligned.m8n8.x4.shared.b16 {%0,%1,%2,%3}, [%4];"
        : "=r"(r[0]), "=r"(r[1]), "=r"(r[2]), "=r"(r[3]) : "r"(addr));
}
__device__ __forceinline__ void mma_f16(float* d, const uint32_t* a, const uint32_t* b) {
    asm volatile(
        "mma.sync.aligned.m16n8k16.row.col.f32.f16.f16.f32 "
        "{%0,%1,%2,%3}, {%4,%5,%6,%7}, {%8,%9}, {%0,%1,%2,%3};"
        : "+f"(d[0]), "+f"(d[1]), "+f"(d[2]), "+f"(d[3])
        : "r"(a[0]), "r"(a[1]), "r"(a[2]), "r"(a[3]), "r"(b[0]), "r"(b[1]));
}

// split 4 floats -> hi/lo fp16 packed pairs
__device__ __forceinline__ void split4(const float* f, uint2* hi, uint2* lo) {
    __half h0 = __float2half_rn(f[0]), h1 = __float2half_rn(f[1]);
    __half h2 = __float2half_rn(f[2]), h3 = __float2half_rn(f[3]);
    __half l0 = __float2half_rn(f[0] - __half2float(h0));
    __half l1 = __float2half_rn(f[1] - __half2float(h1));
    __half l2 = __float2half_rn(f[2] - __half2float(h2));
    __half l3 = __float2half_rn(f[3] - __half2float(h3));
    hi->x = (uint32_t)__half_as_ushort(h0) | ((uint32_t)__half_as_ushort(h1) << 16);
    hi->y = (uint32_t)__half_as_ushort(h2) | ((uint32_t)__half_as_ushort(h3) << 16);
    lo->x = (uint32_t)__half_as_ushort(l0) | ((uint32_t)__half_as_ushort(l1) << 16);
    lo->y = (uint32_t)__half_as_ushort(l2) | ((uint32_t)__half_as_ushort(l3) << 16);
}
__device__ __forceinline__ uint32_t packh2(float a, float b) {
    return (uint32_t)__half_as_ushort(__float2half_rn(a)) |
           ((uint32_t)__half_as_ushort(__float2half_rn(b)) << 16);
}
__device__ __forceinline__ float h2lo_res(uint32_t h, float a) {
    return a - __half2float(__ushort_as_half((unsigned short)(h & 0xffff)));
}

// ============================================================================
// HMMA GEMM (unchanged from round 5 — measured 49.4% tensor)
// ============================================================================
#define GEMM_SMEM 65536

__device__ __forceinline__ void split_store(char* smem_hi_base, uint32_t off, float4 v) {
    float f[4] = {v.x, v.y, v.z, v.w};
    uint2 hi, lo;
    split4(f, &hi, &lo);
    *(uint2*)(smem_hi_base + off)         = hi;
    *(uint2*)(smem_hi_base + 16384 + off) = lo;
}

__global__ __launch_bounds__(256, 2) void gemm_hmma_kernel(
    const float* __restrict__ A0, const float* __restrict__ A1, const float* __restrict__ A2,
    const float* __restrict__ W0, const float* __restrict__ W1, const float* __restrict__ W2,
    const float* __restrict__ bi0, const float* __restrict__ bi1, const float* __restrict__ bi2,
    float* __restrict__ C0, float* __restrict__ C1, float* __restrict__ C2, int mode)
{
    extern __shared__ char sm[];
    const uint32_t smb = smem_u32(sm);
    const int tid = threadIdx.x;
    const int lane = tid & 31;
    const int wid = tid >> 5;
    const int wm = wid >> 2;
    const int wn = wid & 3;
    const int z = blockIdx.z;
    const float* A = (z == 0) ? A0 : (z == 1) ? A1 : A2;
    const float* W = (z == 0) ? W0 : (z == 1) ? W1 : W2;
    const float* bias = (z == 0) ? bi0 : (z == 1) ? bi1 : bi2;
    float* C = (z == 0) ? C0 : (z == 1) ? C1 : C2;

    const int m0 = blockIdx.y * 128;
    const int n0 = blockIdx.x * 128;

    float acc[4][4][4];
    #pragma unroll
    for (int i = 0; i < 4; i++)
        #pragma unroll
        for (int j = 0; j < 4; j++)
            #pragma unroll
            for (int t = 0; t < 4; t++) acc[i][j][t] = 0.f;

    const int a_m = lane & 15;
    const int a_kb = (lane >> 4) * 16;
    const int b_n = (lane & 7) + ((lane >> 4) & 1) * 8;
    const int b_kb = ((lane >> 3) & 1) * 16;

    const int lrow = tid >> 4;
    const int lc4 = (tid & 15) * 4;

    for (int ch = 0; ch < 16; ch++) {
        const int k0 = ch * 64;
        __syncthreads();
        #pragma unroll
        for (int i = 0; i < 8; i++) {
            int row = lrow + i * 16;
            float4 av = *(const float4*)(A + (size_t)(m0 + row) * D_ + k0 + lc4);
            float4 wv = *(const float4*)(W + (size_t)(n0 + row) * D_ + k0 + lc4);
            uint32_t off = sw128((uint32_t)(row * 128 + lc4 * 2));
            split_store(sm, off, av);
            split_store(sm + 32768, off, wv);
        }
        __syncthreads();

        #pragma unroll
        for (int ks = 0; ks < 4; ks++) {
            uint32_t afh[4][4], afl[4][4];
            #pragma unroll
            for (int mt = 0; mt < 4; mt++) {
                uint32_t byte = (uint32_t)((wm * 64 + mt * 16 + a_m) * 128 + ks * 32 + a_kb);
                uint32_t ad = smb + sw128(byte);
                ldsm_x4(afh[mt], ad);
                ldsm_x4(afl[mt], ad + 16384);
            }
            uint32_t bfh[2][4], bfl[2][4];
            #pragma unroll
            for (int bt = 0; bt < 2; bt++) {
                uint32_t byte = (uint32_t)((wn * 32 + bt * 16 + b_n) * 128 + ks * 32 + b_kb);
                uint32_t bd = smb + 32768 + sw128(byte);
                ldsm_x4(bfh[bt], bd);
                ldsm_x4(bfl[bt], bd + 16384);
            }
            #pragma unroll
            for (int mt = 0; mt < 4; mt++)
                #pragma unroll
                for (int nt = 0; nt < 4; nt++) {
                    const uint32_t* bh = &bfh[nt >> 1][(nt & 1) * 2];
                    const uint32_t* bl = &bfl[nt >> 1][(nt & 1) * 2];
                    mma_f16(acc[mt][nt], afh[mt], bh);
                    mma_f16(acc[mt][nt], afh[mt], bl);
                    mma_f16(acc[mt][nt], afl[mt], bh);
                }
        }
    }

    const int g = lane >> 2;
    const int q2 = (lane & 3) * 2;
    #pragma unroll
    for (int mt = 0; mt < 4; mt++) {
        #pragma unroll
        for (int nt = 0; nt < 4; nt++) {
            int mr = m0 + wm * 64 + mt * 16 + g;
            int nc = n0 + wn * 32 + nt * 8 + q2;
            float2 b2 = *(const float2*)(bias + nc);
            #pragma unroll
            for (int half = 0; half < 2; half++) {
                int m = mr + half * 8;
                float2 o = make_float2(acc[mt][nt][half * 2 + 0] + b2.x,
                                       acc[mt][nt][half * 2 + 1] + b2.y);
                float* dst;
                if (mode == 0) {
                    dst = C + (size_t)m * D_ + nc;
                } else {
                    int b = m >> 11, s = m & 2047, h = nc >> 6, hd = nc & 63;
                    dst = C + (((size_t)(b * H_ + h) * S_ + s) << 6) + hd;
                }
                *(float2*)dst = o;
            }
        }
    }
}

// ============================================================================
// Flash attention with HMMA (fp16 hi/lo, 3-term) — 128q x 64k tiles, 8 warps.
// smem: QHI@0(16K,SW128) QLO@16K  KHI@32K(8K,SW128) KLO@40K
//       VTHI@48K (64 rows x 144B pitch, Vt[d][j]) VTLO@57216
// ============================================================================
#define F_QHI 0
#define F_QLO 16384
#define F_KHI 32768
#define F_KLO 40960
#define F_VHI 49152
#define F_VLO 58368
#define VT_PITCH 144
#define FLASH_SMEM (F_VLO + 9216)   // 67584

__global__ __launch_bounds__(256, 2) void flash_kernel(
    const float* __restrict__ Qh, const float* __restrict__ Kh,
    const float* __restrict__ Vh, float* __restrict__ Out)
{
    extern __shared__ char smc[];
    const uint32_t smb = smem_u32(smc);
    const int tid = threadIdx.x;
    const int lane = tid & 31;
    const int w = tid >> 5;                 // warp: rows w*16..w*16+15
    const int g = lane >> 2;                // fragment row within 8
    const int q = lane & 3;                 // fragment col pair
    const int bh = blockIdx.y;
    const int qblk = (int)gridDim.x - 1 - (int)blockIdx.x;
    const int q0 = qblk * 128;

    const float* Qbase = Qh + ((size_t)bh * S_ + q0) * HD_;
    const float* Kbase = Kh + (size_t)bh * S_ * HD_;
    const float* Vbase = Vh + (size_t)bh * S_ * HD_;

    // ---- load Q tile (128x64) as fp16 hi/lo, SW128 ----
    {
        const int lrow = tid >> 4;
        const int lc4 = (tid & 15) * 4;
        #pragma unroll
        for (int i = 0; i < 8; i++) {
            int row = lrow + i * 16;
            float4 v = *(const float4*)(Qbase + (size_t)row * HD_ + lc4);
            float f[4] = {v.x, v.y, v.z, v.w};
            uint2 hi, lo;
            split4(f, &hi, &lo);
            uint32_t off = sw128((uint32_t)(row * 128 + lc4 * 2));
            *(uint2*)(smc + F_QHI + off) = hi;
            *(uint2*)(smc + F_QLO + off) = lo;
        }
    }

    // softmax state: rows r0 = q0+w*16+g, r1 = r0+8
    float m_st[2] = {-1e30f, -1e30f};
    float l_st[2] = {0.f, 0.f};
    float o[8][4];
    #pragma unroll
    for (int t = 0; t < 8; t++)
        #pragma unroll
        for (int e = 0; e < 4; e++) o[t][e] = 0.f;

    // ldmatrix lane components (identical to GEMM kernel)
    const int a_m = lane & 15;
    const int a_kb = (lane >> 4) * 16;
    const int b_n = (lane & 7) + ((lane >> 4) & 1) * 8;
    const int b_kb = ((lane >> 3) & 1) * 16;
    // Vt ldmatrix (non-swizzled, pitch 144): same structure
    const int v_row = (lane & 7) + ((lane >> 4) & 1) * 8;
    const int v_cb = ((lane >> 3) & 1) * 16;

    const int nkb = 2 * qblk + 2;
    for (int kb = 0; kb < nkb; kb++) {
        const int k0 = kb * 64;
        __syncthreads();
        // ---- load K tile (64x64) fp16 hi/lo SW128 ----
        {
            const int j = tid >> 2;                  // 0..63
            const int c4 = (tid & 3) * 16;           // 0,16,32,48
            #pragma unroll
            for (int i = 0; i < 4; i++) {
                int cc = c4 + i * 4;
                float4 v = *(const float4*)(Kbase + (size_t)(k0 + j) * HD_ + cc);
                float f[4] = {v.x, v.y, v.z, v.w};
                uint2 hi, lo;
                split4(f, &hi, &lo);
                uint32_t off = sw128((uint32_t)(j * 128 + cc * 2));
                *(uint2*)(smc + F_KHI + off) = hi;
                *(uint2*)(smc + F_KLO + off) = lo;
            }
        }
        // ---- load V tile transposed: Vt[d][j], pitch 144B ----
        {
            const int d0 = (tid & 15) * 4;
            const int j0 = (tid >> 4) * 4;
            float4 vv[4];
            #pragma unroll
            for (int jj = 0; jj < 4; jj++)
                vv[jj] = *(const float4*)(Vbase + (size_t)(k0 + j0 + jj) * HD_ + d0);
            const float* vf = (const float*)vv;      // vf[jj*4 + dd]
            #pragma unroll
            for (int dd = 0; dd < 4; dd++) {
                float f[4] = {vf[0 * 4 + dd], vf[1 * 4 + dd], vf[2 * 4 + dd], vf[3 * 4 + dd]};
                uint2 hi, lo;
                split4(f, &hi, &lo);
                uint32_t off = (uint32_t)((d0 + dd) * VT_PITCH + j0 * 2);
                *(uint2*)(smc + F_VHI + off) = hi;
                *(uint2*)(smc + F_VLO + off) = lo;
            }
        }
        __syncthreads();

        // ---- S = Q K^T (fp32 acc, 3-term) ----
        float s[8][4];
        #pragma unroll
        for (int t = 0; t < 8; t++)
            #pragma unroll
            for (int e = 0; e < 4; e++) s[t][e] = 0.f;

        #pragma unroll
        for (int ks = 0; ks < 4; ks++) {
            uint32_t ah[4], al[4];
            {
                uint32_t byte = (uint32_t)((w * 16 + a_m) * 128 + ks * 32 + a_kb);
                uint32_t ad = smb + F_QHI + sw128(byte);
                ldsm_x4(ah, ad);
                ldsm_x4(al, ad + 16384);
            }
            uint32_t bfh[4][4], bfl[4][4];
            #pragma unroll
            for (int bt = 0; bt < 4; bt++) {
                uint32_t byte = (uint32_t)((bt * 16 + b_n) * 128 + ks * 32 + b_kb);
                uint32_t bd = smb + F_KHI + sw128(byte);
                ldsm_x4(bfh[bt], bd);
                ldsm_x4(bfl[bt], bd + 8192);
            }
            #pragma unroll
            for (int t = 0; t < 8; t++) {
                const uint32_t* bh = &bfh[t >> 1][(t & 1) * 2];
                const uint32_t* bl = &bfl[t >> 1][(t & 1) * 2];
                mma_f16(s[t], ah, bh);
                mma_f16(s[t], ah, bl);
                mma_f16(s[t], al, bh);
            }
        }

        // ---- scale + causal mask ----
        const int r0g = q0 + w * 16 + g;
        const bool need_mask = (k0 + 64 > q0 + w * 16);
        #pragma unroll
        for (int t = 0; t < 8; t++) {
            int jc = k0 + t * 8 + q * 2;
            #pragma unroll
            for (int e = 0; e < 4; e++) {
                int row = r0g + (e >> 1) * 8;
                int col = jc + (e & 1);
                float v = s[t][e] * 0.125f;
                if (need_mask && col > row) v = -1e30f;
                s[t][e] = v;
            }
        }

        // ---- online softmax (2 rows per thread) ----
        float mnew[2] = {-1e30f, -1e30f};
        #pragma unroll
        for (int t = 0; t < 8; t++) {
            mnew[0] = fmaxf(mnew[0], fmaxf(s[t][0], s[t][1]));
            mnew[1] = fmaxf(mnew[1], fmaxf(s[t][2], s[t][3]));
        }
        #pragma unroll
        for (int off = 1; off < 4; off <<= 1) {
            mnew[0] = fmaxf(mnew[0], __shfl_xor_sync(0xffffffffu, mnew[0], off));
            mnew[1] = fmaxf(mnew[1], __shfl_xor_sync(0xffffffffu, mnew[1], off));
        }
        float ms[2], sum[2] = {0.f, 0.f};
        #pragma unroll
        for (int r = 0; r < 2; r++) {
            mnew[r] = fmaxf(m_st[r], mnew[r]);
            ms[r] = __expf(m_st[r] - mnew[r]);
            m_st[r] = mnew[r];
        }
        #pragma unroll
        for (int t = 0; t < 8; t++) {
            s[t][0] = __expf(s[t][0] - mnew[0]);
            s[t][1] = __expf(s[t][1] - mnew[0]);
            s[t][2] = __expf(s[t][2] - mnew[1]);
            s[t][3] = __expf(s[t][3] - mnew[1]);
            sum[0] += s[t][0] + s[t][1];
            sum[1] += s[t][2] + s[t][3];
        }
        #pragma unroll
        for (int off = 1; off < 4; off <<= 1) {
            sum[0] += __shfl_xor_sync(0xffffffffu, sum[0], off);
            sum[1] += __shfl_xor_sync(0xffffffffu, sum[1], off);
        }
        l_st[0] = l_st[0] * ms[0] + sum[0];
        l_st[1] = l_st[1] * ms[1] + sum[1];

        // rescale O
        #pragma unroll
        for (int t = 0; t < 8; t++) {
            o[t][0] *= ms[0]; o[t][1] *= ms[0];
            o[t][2] *= ms[1]; o[t][3] *= ms[1];
        }

        // ---- O += P V : P from registers (hi/lo), B from Vt ----
        #pragma unroll
        for (int ks = 0; ks < 4; ks++) {
            // P A-fragments: k-cols 16ks..16ks+15 from score tiles 2ks, 2ks+1
            uint32_t ph[4], pl[4];
            {
                const float* t0 = s[2 * ks];
                const float* t1 = s[2 * ks + 1];
                ph[0] = packh2(t0[0], t0[1]);
                ph[1] = packh2(t0[2], t0[3]);
                ph[2] = packh2(t1[0], t1[1]);
                ph[3] = packh2(t1[2], t1[3]);
                pl[0] = packh2(h2lo_res(ph[0], t0[0]), t0[1] - __half2float(__ushort_as_half((unsigned short)(ph[0] >> 16))));
                pl[1] = packh2(h2lo_res(ph[1], t0[2]), t0[3] - __half2float(__ushort_as_half((unsigned short)(ph[1] >> 16))));
                pl[2] = packh2(h2lo_res(ph[2], t1[0]), t1[1] - __half2float(__ushort_as_half((unsigned short)(ph[2] >> 16))));
                pl[3] = packh2(h2lo_res(ph[3], t1[2]), t1[3] - __half2float(__ushort_as_half((unsigned short)(ph[3] >> 16))));
            }
            // Vt B-fragments: 4 x4 loads cover d=64 (8 n8-tiles)
            uint32_t vfh[4][4], vfl[4][4];
            #pragma unroll
            for (int bt = 0; bt < 4; bt++) {
                uint32_t off = (uint32_t)((bt * 16 + v_row) * VT_PITCH + ks * 32 + v_cb);
                ldsm_x4(vfh[bt], smb + F_VHI + off);
                ldsm_x4(vfl[bt], smb + F_VLO + off);
            }
            #pragma unroll
            for (int t = 0; t < 8; t++) {
                const uint32_t* bh = &vfh[t >> 1][(t & 1) * 2];
                const uint32_t* bl = &vfl[t >> 1][(t & 1) * 2];
                mma_f16(o[t], ph, bh);
                mma_f16(o[t], ph, bl);
                mma_f16(o[t], pl, bh);
            }
        }
    }

    // ---- epilogue: divide by l, write [B,S,D] ----
    const int b = bh >> 4;
    const int h = bh & 15;
    const float inv0 = 1.f / l_st[0];
    const float inv1 = 1.f / l_st[1];
    #pragma unroll
    for (int t = 0; t < 8; t++) {
        int dc = t * 8 + q * 2;
        int gs0 = q0 + w * 16 + g;
        *(float2*)(Out + ((size_t)(b * S_ + gs0)) * D_ + h * 64 + dc) =
            make_float2(o[t][0] * inv0, o[t][1] * inv0);
        *(float2*)(Out + ((size_t)(b * S_ + gs0 + 8)) * D_ + h * 64 + dc) =
            make_float2(o[t][2] * inv1, o[t][3] * inv1);
    }
}

// ============================================================================
// Launch
// ============================================================================
extern "C" void kernel_launch(void* const* d_in, const int* in_sizes, int n_in,
                              void* d_out, int out_size)
{
    const float* q  = (const float*)d_in[0];
    const float* k  = (const float*)d_in[1];
    const float* v  = (const float*)d_in[2];
    const float* Wq = (const float*)d_in[4];
    const float* bq = (const float*)d_in[5];
    const float* Wk = (const float*)d_in[6];
    const float* bk = (const float*)d_in[7];
    const float* Wv = (const float*)d_in[8];
    const float* bv = (const float*)d_in[9];
    const float* Wo = (const float*)d_in[10];
    const float* bo = (const float*)d_in[11];

    float* out = (float*)d_out;
    float* kh  = out + OUT_ELEMS;
    float* vh  = out + 2 * OUT_ELEMS;

    float* qh;   cudaGetSymbolAddress((void**)&qh,   g_qh);
    float* attn; cudaGetSymbolAddress((void**)&attn, g_attn);

    cudaFuncSetAttribute(gemm_hmma_kernel,
                         cudaFuncAttributeMaxDynamicSharedMemorySize, GEMM_SMEM);
    cudaFuncSetAttribute(flash_kernel,
                         cudaFuncAttributeMaxDynamicSharedMemorySize, FLASH_SMEM);

    dim3 qkv_grid(D_ / 128, M_ / 128, 3);
    gemm_hmma_kernel<<<qkv_grid, 256, GEMM_SMEM>>>(
        q, k, v, Wq, Wk, Wv, bq, bk, bv, qh, kh, vh, 1);

    flash_kernel<<<dim3(S_ / 128, B_ * H_), 256, FLASH_SMEM>>>(qh, kh, vh, attn);

    dim3 o_grid(D_ / 128, M_ / 128, 1);
    gemm_hmma_kernel<<<o_grid, 256, GEMM_SMEM>>>(
        attn, attn, attn, Wo, Wo, Wo, bo, bo, bo, out, out, out, 0);
}